// round 2
// baseline (speedup 1.0000x reference)
#include <cuda_runtime.h>
#include <math.h>

#define Bsz 8192
#define Dd  1024
#define Rr  64
#define TB  16
#define NT  512

// ---- Yoshida 4th-order coefficients (double-precision, then rounded once to f32,
//      matching JAX's python-double scalar folding before the f32 broadcast) ----
constexpr double kCbrt2 = 1.2599210498948731647672106072782;
constexpr double kW1 = 1.0 / (2.0 - kCbrt2);
constexpr double kW0 = -kCbrt2 * kW1;
constexpr double kDT = 0.01;   // DT * DT_SCALE

#define C1DT ((float)((kW1 * 0.5) * kDT))
#define C2DT ((float)(((kW0 + kW1) * 0.5) * kDT))
#define C3DT C2DT
#define C4DT C1DT
#define D1DT ((float)(kW1 * kDT))
#define D2DT ((float)(kW0 * kDT))
#define D3DT D1DT

#define PLASTICITY   0.1f
#define SING_THRESH  10.0f
#define SING_STRENGTH 20.0f

__global__ void __launch_bounds__(NT, 1)
yoshida_kernel(const float* __restrict__ x_in,
               const float* __restrict__ v_in,
               const float* __restrict__ force,
               const float* __restrict__ U,     // [D, R]
               const float* __restrict__ Wm,    // [R, D]
               const float* __restrict__ Vw,    // [D, R]
               const int*   __restrict__ steps_p,
               float* __restrict__ out)         // [x(B*D) ; v(B*D)]
{
    extern __shared__ float smem[];
    float* xs     = smem;                 // TB*Dd
    float* vs     = smem + TB * Dd;       // TB*Dd
    float* qs     = vs   + TB * Dd;       // Rr*TB  (layout qs[r*TB + row])
    float* sing_s = qs   + Rr * TB;       // TB

    const int tid  = threadIdx.x;
    const int row0 = blockIdx.x * TB;

    float4* sx4 = (float4*)xs;
    float4* sv4 = (float4*)vs;

    // ---- load state tile into SMEM ----
    {
        const float4* gx = (const float4*)(x_in + (size_t)row0 * Dd);
        const float4* gv = (const float4*)(v_in + (size_t)row0 * Dd);
        #pragma unroll
        for (int i = tid; i < TB * Dd / 4; i += NT) {
            sx4[i] = gx[i];
            sv4[i] = gv[i];
        }
    }

    const int nsteps = *steps_p;

    for (int s = 0; s < nsteps; ++s) {
        #pragma unroll
        for (int sub = 0; sub < 3; ++sub) {
            const float cdt = (sub == 0) ? C1DT : (sub == 1) ? C2DT : C3DT;
            const float ddt = (sub == 0) ? D1DT : (sub == 1) ? D2DT : D3DT;

            // ---- drift: x += cdt * v ----
            __syncthreads();
            #pragma unroll
            for (int i = tid; i < TB * Dd / 4; i += NT) {
                float4 xv = sx4[i];
                const float4 vv = sv4[i];
                xv.x += cdt * vv.x; xv.y += cdt * vv.y;
                xv.z += cdt * vv.z; xv.w += cdt * vv.w;
                sx4[i] = xv;
            }
            __syncthreads();

            // ---- kick phase 1: xn2 per row -> sing_s (one warp per row) ----
            {
                const int row  = tid >> 5;
                const int lane = tid & 31;
                const float4* xr = (const float4*)(xs + row * Dd);
                float acc = 0.0f;
                #pragma unroll
                for (int i = 0; i < 8; ++i) {
                    const float4 xv = xr[lane + i * 32];
                    acc += xv.x * xv.x + xv.y * xv.y + xv.z * xv.z + xv.w * xv.w;
                }
                #pragma unroll
                for (int o = 16; o; o >>= 1)
                    acc += __shfl_xor_sync(0xffffffffu, acc, o);
                if (lane == 0)
                    sing_s[row] = 1.0f + SING_STRENGTH * expf(-acc * (1.0f / SING_THRESH));
            }

            // ---- kick phase 2: P = v.U, M = x.Vw ; q = P^2 * (1 + 0.1*tanh(M)) ----
            {
                const int r = tid & 63;
                const int g = tid >> 6;          // 0..7 -> rows {g, g+8}
                const float* __restrict__ v0 = vs + (g    ) * Dd;
                const float* __restrict__ v1 = vs + (g + 8) * Dd;
                const float* __restrict__ x0 = xs + (g    ) * Dd;
                const float* __restrict__ x1 = xs + (g + 8) * Dd;

                float p0 = 0.f, p1 = 0.f, m0 = 0.f, m1 = 0.f;
                #pragma unroll 2
                for (int d = 0; d < Dd; d += 4) {
                    const float* up = U  + (size_t)d * Rr + r;
                    const float* wp = Vw + (size_t)d * Rr + r;
                    const float u0 = up[0], u1 = up[Rr], u2 = up[2 * Rr], u3 = up[3 * Rr];
                    const float w0 = wp[0], w1 = wp[Rr], w2 = wp[2 * Rr], w3 = wp[3 * Rr];
                    float4 t;
                    t = *(const float4*)(v0 + d);
                    p0 += t.x * u0 + t.y * u1 + t.z * u2 + t.w * u3;
                    t = *(const float4*)(v1 + d);
                    p1 += t.x * u0 + t.y * u1 + t.z * u2 + t.w * u3;
                    t = *(const float4*)(x0 + d);
                    m0 += t.x * w0 + t.y * w1 + t.z * w2 + t.w * w3;
                    t = *(const float4*)(x1 + d);
                    m1 += t.x * w0 + t.y * w1 + t.z * w2 + t.w * w3;
                }
                qs[r * TB + g    ] = p0 * p0 * (1.0f + PLASTICITY * tanhf(m0));
                qs[r * TB + g + 8] = p1 * p1 * (1.0f + PLASTICITY * tanhf(m1));
            }
            __syncthreads();

            // ---- kick phase 3: gamma = q.W ; v += ddt * (force - gamma*sing) ----
            {
                const int kk = (tid & 127) * 4;       // 128 k-threads * 4 k = 512 k / pass
                const int g4 = (tid >> 7) * 4;        // rows g4..g4+3
                #pragma unroll
                for (int pass = 0; pass < 2; ++pass) {
                    const int k0 = pass * 512 + kk;
                    float4 a0 = {0,0,0,0}, a1 = {0,0,0,0}, a2 = {0,0,0,0}, a3 = {0,0,0,0};
                    #pragma unroll 8
                    for (int r = 0; r < Rr; ++r) {
                        const float4 w = *(const float4*)(Wm + (size_t)r * Dd + k0);
                        const float4 q = *(const float4*)(qs + r * TB + g4);
                        a0.x += q.x * w.x; a0.y += q.x * w.y; a0.z += q.x * w.z; a0.w += q.x * w.w;
                        a1.x += q.y * w.x; a1.y += q.y * w.y; a1.z += q.y * w.z; a1.w += q.y * w.w;
                        a2.x += q.z * w.x; a2.y += q.z * w.y; a2.z += q.z * w.z; a2.w += q.z * w.w;
                        a3.x += q.w * w.x; a3.y += q.w * w.y; a3.z += q.w * w.z; a3.w += q.w * w.w;
                    }
                    #pragma unroll
                    for (int j = 0; j < 4; ++j) {
                        const int row = g4 + j;
                        const float sg = sing_s[row];
                        const float4 a = (j == 0) ? a0 : (j == 1) ? a1 : (j == 2) ? a2 : a3;
                        const float4 f = *(const float4*)(force + (size_t)(row0 + row) * Dd + k0);
                        float4* vp = (float4*)(vs + row * Dd + k0);
                        float4 vv = *vp;
                        vv.x += ddt * (f.x - a.x * sg);
                        vv.y += ddt * (f.y - a.y * sg);
                        vv.z += ddt * (f.z - a.z * sg);
                        vv.w += ddt * (f.w - a.w * sg);
                        *vp = vv;
                    }
                }
            }
        }

        // ---- final drift of the step: x += C4*dt * v ----
        __syncthreads();
        #pragma unroll
        for (int i = tid; i < TB * Dd / 4; i += NT) {
            float4 xv = sx4[i];
            const float4 vv = sv4[i];
            xv.x += C4DT * vv.x; xv.y += C4DT * vv.y;
            xv.z += C4DT * vv.z; xv.w += C4DT * vv.w;
            sx4[i] = xv;
        }
    }

    // ---- store: out = [x ; v] ----
    __syncthreads();
    {
        float4* ox = (float4*)(out + (size_t)row0 * Dd);
        float4* ov = (float4*)(out + (size_t)Bsz * Dd + (size_t)row0 * Dd);
        #pragma unroll
        for (int i = tid; i < TB * Dd / 4; i += NT) {
            ox[i] = sx4[i];
            ov[i] = sv4[i];
        }
    }
}

extern "C" void kernel_launch(void* const* d_in, const int* in_sizes, int n_in,
                              void* d_out, int out_size) {
    const float* x     = (const float*)d_in[0];
    const float* v     = (const float*)d_in[1];
    const float* force = (const float*)d_in[2];
    const float* U     = (const float*)d_in[3];
    const float* W     = (const float*)d_in[4];
    const float* Vw    = (const float*)d_in[5];
    const int*   steps = (const int*)d_in[6];

    const size_t smem = (size_t)(2 * TB * Dd + Rr * TB + TB) * sizeof(float);
    cudaFuncSetAttribute(yoshida_kernel,
                         cudaFuncAttributeMaxDynamicSharedMemorySize, (int)smem);
    yoshida_kernel<<<Bsz / TB, NT, smem>>>(x, v, force, U, W, Vw, steps, (float*)d_out);
}

// round 3
// speedup vs baseline: 1.1634x; 1.1634x over previous
#include <cuda_runtime.h>
#include <math.h>

#define Bsz 8192
#define Dd  1024
#define Rr  64
#define TB  16
#define NT  512

typedef unsigned long long ull;

// ---- Yoshida 4th-order coefficients ----
constexpr double kCbrt2 = 1.2599210498948731647672106072782;
constexpr double kW1 = 1.0 / (2.0 - kCbrt2);
constexpr double kW0 = -kCbrt2 * kW1;
constexpr double kDT = 0.01;

#define C1DT ((float)((kW1 * 0.5) * kDT))
#define C2DT ((float)(((kW0 + kW1) * 0.5) * kDT))
#define C3DT C2DT
#define C4DT C1DT
#define D1DT ((float)(kW1 * kDT))
#define D2DT ((float)(kW0 * kDT))
#define D3DT D1DT

#define PLASTICITY    0.1f
#define SING_THRESH   10.0f
#define SING_STRENGTH 20.0f

// ---- packed f32x2 helpers (Blackwell) ----
__device__ __forceinline__ ull splat2(float x) {
    ull r; asm("mov.b64 %0, {%1, %1};" : "=l"(r) : "f"(x)); return r;
}
__device__ __forceinline__ ull fma2(ull a, ull b, ull c) {
    ull d; asm("fma.rn.f32x2 %0, %1, %2, %3;" : "=l"(d) : "l"(a), "l"(b), "l"(c)); return d;
}
__device__ __forceinline__ ull add2(ull a, ull b) {
    ull d; asm("add.rn.f32x2 %0, %1, %2;" : "=l"(d) : "l"(a), "l"(b)); return d;
}
__device__ __forceinline__ float2 unpk2(ull v) {
    float2 r; asm("mov.b64 {%0, %1}, %2;" : "=f"(r.x), "=f"(r.y) : "l"(v)); return r;
}

__global__ void __launch_bounds__(NT, 1)
yoshida_kernel(const float* __restrict__ x_in,
               const float* __restrict__ v_in,
               const float* __restrict__ force,
               const float* __restrict__ U,     // [D, R]
               const float* __restrict__ Wm,    // [R, D]
               const float* __restrict__ Vw,    // [D, R]
               const int*   __restrict__ steps_p,
               float* __restrict__ out)         // [x(B*D) ; v(B*D)]
{
    extern __shared__ float smem[];
    float* xs     = smem;                         // 16384
    float* vs     = xs + TB * Dd;                 // 16384
    float* qs     = vs + TB * Dd;                 // 1024  (qs[r*TB + row], sing folded in)
    float* sing_s = qs + Rr * TB;                 // 16
    float* part   = sing_s + TB;                  // 2048  (256 threads * 4 ull)

    const int tid  = threadIdx.x;
    const int row0 = blockIdx.x * TB;

    float4* sx4 = (float4*)xs;
    float4* sv4 = (float4*)vs;

    // ---- load state tile ----
    {
        const float4* gx = (const float4*)(x_in + (size_t)row0 * Dd);
        const float4* gv = (const float4*)(v_in + (size_t)row0 * Dd);
        #pragma unroll
        for (int i = tid; i < TB * Dd / 4; i += NT) {
            sx4[i] = gx[i];
            sv4[i] = gv[i];
        }
    }

    const int nsteps = *steps_p;

    // phase-2 thread mapping
    const int rq   = (tid & 15) * 4;          // r's rq..rq+3
    const int p2row = (tid >> 4) & 15;        // row
    const int dh   = tid >> 8;                // d-half 0/1
    // phase-3 thread mapping
    const int kk = (tid & 127) * 4;
    const int g4 = (tid >> 7) * 4;            // rows g4..g4+3

    for (int s = 0; s < nsteps; ++s) {
        #pragma unroll
        for (int sub = 0; sub < 3; ++sub) {
            const float cdt = (sub == 0) ? C1DT : (sub == 1) ? C2DT : C3DT;
            const float ddt = (sub == 0) ? D1DT : (sub == 1) ? D2DT : D3DT;

            // ---- drift: x += cdt * v ----
            __syncthreads();
            #pragma unroll
            for (int i = tid; i < TB * Dd / 4; i += NT) {
                float4 xv = sx4[i];
                const float4 vv = sv4[i];
                xv.x += cdt * vv.x; xv.y += cdt * vv.y;
                xv.z += cdt * vv.z; xv.w += cdt * vv.w;
                sx4[i] = xv;
            }
            __syncthreads();

            // ---- phase 1: xn2 per row -> sing (one warp per row) ----
            {
                const int row  = tid >> 5;
                const int lane = tid & 31;
                const float4* xr = (const float4*)(xs + row * Dd);
                float acc = 0.0f;
                #pragma unroll
                for (int i = 0; i < 8; ++i) {
                    const float4 xv = xr[lane + i * 32];
                    acc += xv.x * xv.x + xv.y * xv.y + xv.z * xv.z + xv.w * xv.w;
                }
                #pragma unroll
                for (int o = 16; o; o >>= 1)
                    acc += __shfl_xor_sync(0xffffffffu, acc, o);
                if (lane == 0)
                    sing_s[row] = 1.0f + SING_STRENGTH * expf(-acc * (1.0f / SING_THRESH));
            }

            // ---- phase 2 main: packed partial dots over this thread's d-half ----
            ull pP01 = 0ull, pP23 = 0ull, pM01 = 0ull, pM23 = 0ull;
            {
                const float* __restrict__ vrow = vs + p2row * Dd + dh * 512;
                const float* __restrict__ xrow = xs + p2row * Dd + dh * 512;
                const float* __restrict__ Up = U  + (size_t)(dh * 512) * Rr + rq;
                const float* __restrict__ Wp = Vw + (size_t)(dh * 512) * Rr + rq;

                #pragma unroll 2
                for (int d = 0; d < 512; d += 4) {
                    const float4 av = *(const float4*)(vrow + d);
                    const float4 ax = *(const float4*)(xrow + d);
                    const float* up = Up + (size_t)d * Rr;
                    const float* wp = Wp + (size_t)d * Rr;
                    #pragma unroll
                    for (int j = 0; j < 4; ++j) {
                        const ulonglong2 u2 = *(const ulonglong2*)(up + (size_t)j * Rr);
                        const ulonglong2 w2 = *(const ulonglong2*)(wp + (size_t)j * Rr);
                        const float aval = (j == 0) ? av.x : (j == 1) ? av.y : (j == 2) ? av.z : av.w;
                        const float xval = (j == 0) ? ax.x : (j == 1) ? ax.y : (j == 2) ? ax.z : ax.w;
                        const ull sv = splat2(aval);
                        const ull sx = splat2(xval);
                        pP01 = fma2(sv, u2.x, pP01);
                        pP23 = fma2(sv, u2.y, pP23);
                        pM01 = fma2(sx, w2.x, pM01);
                        pM23 = fma2(sx, w2.y, pM23);
                    }
                }
            }

            // ---- exchange d-half partials, build q (sing folded in) ----
            if (dh) {
                ull* pp = (ull*)part + (size_t)(tid & 255) * 4;
                pp[0] = pP01; pp[1] = pP23; pp[2] = pM01; pp[3] = pM23;
            }
            __syncthreads();
            if (!dh) {
                const ull* pp = (const ull*)part + (size_t)tid * 4;
                pP01 = add2(pP01, pp[0]);
                pP23 = add2(pP23, pp[1]);
                pM01 = add2(pM01, pp[2]);
                pM23 = add2(pM23, pp[3]);
                const float2 P01 = unpk2(pP01), P23 = unpk2(pP23);
                const float2 M01 = unpk2(pM01), M23 = unpk2(pM23);
                const float sg = sing_s[p2row];
                qs[(rq + 0) * TB + p2row] = P01.x * P01.x * (1.0f + PLASTICITY * tanhf(M01.x)) * sg;
                qs[(rq + 1) * TB + p2row] = P01.y * P01.y * (1.0f + PLASTICITY * tanhf(M01.y)) * sg;
                qs[(rq + 2) * TB + p2row] = P23.x * P23.x * (1.0f + PLASTICITY * tanhf(M23.x)) * sg;
                qs[(rq + 3) * TB + p2row] = P23.y * P23.y * (1.0f + PLASTICITY * tanhf(M23.y)) * sg;
            }
            __syncthreads();

            // ---- phase 3: gamma = q.W (packed over k) ; v += ddt*(force - gamma) ----
            {
                #pragma unroll
                for (int pass = 0; pass < 2; ++pass) {
                    const int k0 = pass * 512 + kk;
                    ull a00 = 0ull, a01 = 0ull, a10 = 0ull, a11 = 0ull;
                    ull a20 = 0ull, a21 = 0ull, a30 = 0ull, a31 = 0ull;
                    #pragma unroll 8
                    for (int r = 0; r < Rr; ++r) {
                        const ulonglong2 w2 = *(const ulonglong2*)(Wm + (size_t)r * Dd + k0);
                        const float4 q4 = *(const float4*)(qs + r * TB + g4);
                        const ull s0 = splat2(q4.x), s1 = splat2(q4.y);
                        const ull s2 = splat2(q4.z), s3 = splat2(q4.w);
                        a00 = fma2(s0, w2.x, a00); a01 = fma2(s0, w2.y, a01);
                        a10 = fma2(s1, w2.x, a10); a11 = fma2(s1, w2.y, a11);
                        a20 = fma2(s2, w2.x, a20); a21 = fma2(s2, w2.y, a21);
                        a30 = fma2(s3, w2.x, a30); a31 = fma2(s3, w2.y, a31);
                    }
                    #pragma unroll
                    for (int j = 0; j < 4; ++j) {
                        const int row = g4 + j;
                        const float2 g01 = unpk2((j == 0) ? a00 : (j == 1) ? a10 : (j == 2) ? a20 : a30);
                        const float2 g23 = unpk2((j == 0) ? a01 : (j == 1) ? a11 : (j == 2) ? a21 : a31);
                        const float4 f = *(const float4*)(force + (size_t)(row0 + row) * Dd + k0);
                        float4* vp = (float4*)(vs + row * Dd + k0);
                        float4 vv = *vp;
                        vv.x += ddt * (f.x - g01.x);
                        vv.y += ddt * (f.y - g01.y);
                        vv.z += ddt * (f.z - g23.x);
                        vv.w += ddt * (f.w - g23.y);
                        *vp = vv;
                    }
                }
            }
        }

        // ---- final drift of the step: x += C4*dt * v ----
        __syncthreads();
        #pragma unroll
        for (int i = tid; i < TB * Dd / 4; i += NT) {
            float4 xv = sx4[i];
            const float4 vv = sv4[i];
            xv.x += C4DT * vv.x; xv.y += C4DT * vv.y;
            xv.z += C4DT * vv.z; xv.w += C4DT * vv.w;
            sx4[i] = xv;
        }
    }

    // ---- store: out = [x ; v] ----
    __syncthreads();
    {
        float4* ox = (float4*)(out + (size_t)row0 * Dd);
        float4* ov = (float4*)(out + (size_t)Bsz * Dd + (size_t)row0 * Dd);
        #pragma unroll
        for (int i = tid; i < TB * Dd / 4; i += NT) {
            ox[i] = sx4[i];
            ov[i] = sv4[i];
        }
    }
}

extern "C" void kernel_launch(void* const* d_in, const int* in_sizes, int n_in,
                              void* d_out, int out_size) {
    const float* x     = (const float*)d_in[0];
    const float* v     = (const float*)d_in[1];
    const float* force = (const float*)d_in[2];
    const float* U     = (const float*)d_in[3];
    const float* W     = (const float*)d_in[4];
    const float* Vw    = (const float*)d_in[5];
    const int*   steps = (const int*)d_in[6];

    const size_t smem = (size_t)(2 * TB * Dd + Rr * TB + TB + 2048) * sizeof(float);
    cudaFuncSetAttribute(yoshida_kernel,
                         cudaFuncAttributeMaxDynamicSharedMemorySize, (int)smem);
    yoshida_kernel<<<Bsz / TB, NT, smem>>>(x, v, force, U, W, Vw, steps, (float*)d_out);
}

// round 4
// speedup vs baseline: 1.9918x; 1.7121x over previous
#include <cuda_runtime.h>
#include <math.h>

#define Bsz 8192
#define Dd  1024
#define Rr  64
#define TB  16
#define NT  512

typedef unsigned long long ull;

// ---- Yoshida 4th-order coefficients ----
constexpr double kCbrt2 = 1.2599210498948731647672106072782;
constexpr double kW1 = 1.0 / (2.0 - kCbrt2);
constexpr double kW0 = -kCbrt2 * kW1;
constexpr double kDT = 0.01;

#define C1DT ((float)((kW1 * 0.5) * kDT))
#define C2DT ((float)(((kW0 + kW1) * 0.5) * kDT))
#define C3DT C2DT
#define C4DT C1DT
#define D1DT ((float)(kW1 * kDT))
#define D2DT ((float)(kW0 * kDT))
#define D3DT D1DT

#define PLASTICITY    0.1f
#define SING_THRESH   10.0f
#define SING_STRENGTH 20.0f

// ---- packed f32x2 helpers (Blackwell) ----
__device__ __forceinline__ ull splat2(float x) {
    ull r; asm("mov.b64 %0, {%1, %1};" : "=l"(r) : "f"(x)); return r;
}
__device__ __forceinline__ ull fma2(ull a, ull b, ull c) {
    ull d; asm("fma.rn.f32x2 %0, %1, %2, %3;" : "=l"(d) : "l"(a), "l"(b), "l"(c)); return d;
}
__device__ __forceinline__ ull add2(ull a, ull b) {
    ull d; asm("add.rn.f32x2 %0, %1, %2;" : "=l"(d) : "l"(a), "l"(b)); return d;
}
__device__ __forceinline__ float2 unpk2(ull v) {
    float2 r; asm("mov.b64 {%0, %1}, %2;" : "=f"(r.x), "=f"(r.y) : "l"(v)); return r;
}

__global__ void __launch_bounds__(NT, 1)
yoshida_kernel(const float* __restrict__ x_in,
               const float* __restrict__ v_in,
               const float* __restrict__ force,
               const float* __restrict__ U,     // [D, R]
               const float* __restrict__ Wm,    // [R, D]
               const float* __restrict__ Vw,    // [D, R]
               const int*   __restrict__ steps_p,
               float* __restrict__ out)         // [x(B*D) ; v(B*D)]
{
    extern __shared__ float smem[];
    float* xs     = smem;                       // 16384 floats
    float* vs     = xs + TB * Dd;               // 16384
    float* qs     = vs + TB * Dd;               // 1024 (qs[r*TB + row], sing folded)
    float* sing_s = qs + Rr * TB;               // 16
    ull*   part   = (ull*)(sing_s + TB);        // 7 * 1024 ull = 57344 B

    const int tid  = threadIdx.x;
    const int row0 = blockIdx.x * TB;

    float4* sx4 = (float4*)xs;
    float4* sv4 = (float4*)vs;

    // ---- load state tile ----
    {
        const float4* gx = (const float4*)(x_in + (size_t)row0 * Dd);
        const float4* gv = (const float4*)(v_in + (size_t)row0 * Dd);
        #pragma unroll
        for (int i = tid; i < TB * Dd / 4; i += NT) {
            sx4[i] = gx[i];
            sv4[i] = gv[i];
        }
    }

    const int nsteps = *steps_p;

    // phase-2 mapping: 16 r-quads x 4 row-quads x 8 d-slices
    const int rqi  = tid & 15;
    const int g2   = (tid >> 4) & 3;
    const int ds   = tid >> 6;           // 0..7
    const int rq   = rqi * 4;
    const int row4 = g2 * 4;
    const int rqg  = tid & 63;           // (rqi, g2) id

    // phase-3 mapping: 128 k-octets x 4 row-quads
    const int k8 = (tid & 127) * 8;
    const int pg = (tid >> 7) * 4;

    for (int s = 0; s < nsteps; ++s) {
        #pragma unroll
        for (int sub = 0; sub < 3; ++sub) {
            const float cdt = (sub == 0) ? C1DT : (sub == 1) ? C2DT : C3DT;
            const float ddt = (sub == 0) ? D1DT : (sub == 1) ? D2DT : D3DT;

            // ---- drift: x += cdt * v ----
            __syncthreads();
            #pragma unroll
            for (int i = tid; i < TB * Dd / 4; i += NT) {
                float4 xv = sx4[i];
                const float4 vv = sv4[i];
                xv.x += cdt * vv.x; xv.y += cdt * vv.y;
                xv.z += cdt * vv.z; xv.w += cdt * vv.w;
                sx4[i] = xv;
            }
            __syncthreads();

            // ---- phase 1: xn2 per row -> sing (one warp per row) ----
            {
                const int row  = tid >> 5;
                const int lane = tid & 31;
                const float4* xr = (const float4*)(xs + row * Dd);
                float acc = 0.0f;
                #pragma unroll
                for (int i = 0; i < 8; ++i) {
                    const float4 xv = xr[lane + i * 32];
                    acc += xv.x * xv.x + xv.y * xv.y + xv.z * xv.z + xv.w * xv.w;
                }
                #pragma unroll
                for (int o = 16; o; o >>= 1)
                    acc += __shfl_xor_sync(0xffffffffu, acc, o);
                if (lane == 0)
                    sing_s[row] = 1.0f + SING_STRENGTH * expf(-acc * (1.0f / SING_THRESH));
            }

            // ---- phase 2: P = v.U, M = x.Vw for 4 rows x 4 r's over 128 d ----
            // acc layout: A[0..7] = P[row j][half h] (idx j*2+h), A[8..15] = M
            ull A[16];
            #pragma unroll
            for (int c = 0; c < 16; ++c) A[c] = 0ull;
            {
                const int d0 = ds * 128;
                const float* __restrict__ Up = U  + (size_t)d0 * Rr + rq;
                const float* __restrict__ Vp = Vw + (size_t)d0 * Rr + rq;
                const float* __restrict__ vb = vs + row4 * Dd + d0;
                const float* __restrict__ xb = xs + row4 * Dd + d0;

                #pragma unroll 1
                for (int d = 0; d < 128; d += 4) {
                    float4 vv[4], xx[4];
                    #pragma unroll
                    for (int j = 0; j < 4; ++j) {
                        vv[j] = *(const float4*)(vb + j * Dd + d);
                        xx[j] = *(const float4*)(xb + j * Dd + d);
                    }
                    #pragma unroll
                    for (int dd = 0; dd < 4; ++dd) {
                        const ulonglong2 u2 = *(const ulonglong2*)(Up + (size_t)(d + dd) * Rr);
                        const ulonglong2 w2 = *(const ulonglong2*)(Vp + (size_t)(d + dd) * Rr);
                        #pragma unroll
                        for (int j = 0; j < 4; ++j) {
                            const float vj = (dd == 0) ? vv[j].x : (dd == 1) ? vv[j].y
                                           : (dd == 2) ? vv[j].z : vv[j].w;
                            const float xj = (dd == 0) ? xx[j].x : (dd == 1) ? xx[j].y
                                           : (dd == 2) ? xx[j].z : xx[j].w;
                            const ull sv = splat2(vj);
                            const ull sx = splat2(xj);
                            A[j * 2 + 0]     = fma2(sv, u2.x, A[j * 2 + 0]);
                            A[j * 2 + 1]     = fma2(sv, u2.y, A[j * 2 + 1]);
                            A[8 + j * 2 + 0] = fma2(sx, w2.x, A[8 + j * 2 + 0]);
                            A[8 + j * 2 + 1] = fma2(sx, w2.y, A[8 + j * 2 + 1]);
                        }
                    }
                }
            }

            // ---- reduce the 8 d-slices via SMEM, build q (sing folded) ----
            if (ds != 0) {
                ull* pp = part + (size_t)(ds - 1) * 1024 + rqg;
                #pragma unroll
                for (int c = 0; c < 16; ++c) pp[c * 64] = A[c];
            }
            __syncthreads();
            if (ds == 0) {
                #pragma unroll
                for (int p = 0; p < 7; ++p) {
                    const ull* pp = part + (size_t)p * 1024 + rqg;
                    #pragma unroll
                    for (int c = 0; c < 16; ++c) A[c] = add2(A[c], pp[c * 64]);
                }
                #pragma unroll
                for (int j = 0; j < 4; ++j) {
                    const int row = row4 + j;
                    const float sg = sing_s[row];
                    const float2 p01 = unpk2(A[j * 2 + 0]);
                    const float2 p23 = unpk2(A[j * 2 + 1]);
                    const float2 m01 = unpk2(A[8 + j * 2 + 0]);
                    const float2 m23 = unpk2(A[8 + j * 2 + 1]);
                    qs[(rq + 0) * TB + row] = p01.x * p01.x * (1.0f + PLASTICITY * tanhf(m01.x)) * sg;
                    qs[(rq + 1) * TB + row] = p01.y * p01.y * (1.0f + PLASTICITY * tanhf(m01.y)) * sg;
                    qs[(rq + 2) * TB + row] = p23.x * p23.x * (1.0f + PLASTICITY * tanhf(m23.x)) * sg;
                    qs[(rq + 3) * TB + row] = p23.y * p23.y * (1.0f + PLASTICITY * tanhf(m23.y)) * sg;
                }
            }
            __syncthreads();

            // ---- phase 3: gamma = q.W, 4 rows x 8 k's ; v += ddt*(force - gamma) ----
            {
                ull Acc[4][4];
                #pragma unroll
                for (int j = 0; j < 4; ++j)
                    #pragma unroll
                    for (int h = 0; h < 4; ++h) Acc[j][h] = 0ull;

                #pragma unroll 4
                for (int r = 0; r < Rr; ++r) {
                    const float* wr = Wm + (size_t)r * Dd + k8;
                    const ulonglong2 wlo = *(const ulonglong2*)wr;
                    const ulonglong2 whi = *(const ulonglong2*)(wr + 4);
                    const float4 q4 = *(const float4*)(qs + r * TB + pg);
                    const ull s0 = splat2(q4.x), s1 = splat2(q4.y);
                    const ull s2 = splat2(q4.z), s3 = splat2(q4.w);
                    Acc[0][0] = fma2(s0, wlo.x, Acc[0][0]); Acc[0][1] = fma2(s0, wlo.y, Acc[0][1]);
                    Acc[0][2] = fma2(s0, whi.x, Acc[0][2]); Acc[0][3] = fma2(s0, whi.y, Acc[0][3]);
                    Acc[1][0] = fma2(s1, wlo.x, Acc[1][0]); Acc[1][1] = fma2(s1, wlo.y, Acc[1][1]);
                    Acc[1][2] = fma2(s1, whi.x, Acc[1][2]); Acc[1][3] = fma2(s1, whi.y, Acc[1][3]);
                    Acc[2][0] = fma2(s2, wlo.x, Acc[2][0]); Acc[2][1] = fma2(s2, wlo.y, Acc[2][1]);
                    Acc[2][2] = fma2(s2, whi.x, Acc[2][2]); Acc[2][3] = fma2(s2, whi.y, Acc[2][3]);
                    Acc[3][0] = fma2(s3, wlo.x, Acc[3][0]); Acc[3][1] = fma2(s3, wlo.y, Acc[3][1]);
                    Acc[3][2] = fma2(s3, whi.x, Acc[3][2]); Acc[3][3] = fma2(s3, whi.y, Acc[3][3]);
                }

                #pragma unroll
                for (int j = 0; j < 4; ++j) {
                    const int row = pg + j;
                    const float* fp = force + (size_t)(row0 + row) * Dd + k8;
                    const float4 f0 = *(const float4*)(fp);
                    const float4 f1 = *(const float4*)(fp + 4);
                    const float2 g0 = unpk2(Acc[j][0]);
                    const float2 g1 = unpk2(Acc[j][1]);
                    const float2 g2v = unpk2(Acc[j][2]);
                    const float2 g3 = unpk2(Acc[j][3]);
                    float4* vp0 = (float4*)(vs + row * Dd + k8);
                    float4* vp1 = vp0 + 1;
                    float4 v0 = *vp0, v1 = *vp1;
                    v0.x += ddt * (f0.x - g0.x);
                    v0.y += ddt * (f0.y - g0.y);
                    v0.z += ddt * (f0.z - g1.x);
                    v0.w += ddt * (f0.w - g1.y);
                    v1.x += ddt * (f1.x - g2v.x);
                    v1.y += ddt * (f1.y - g2v.y);
                    v1.z += ddt * (f1.z - g3.x);
                    v1.w += ddt * (f1.w - g3.y);
                    *vp0 = v0;
                    *vp1 = v1;
                }
            }
        }

        // ---- final drift of the step: x += C4*dt * v ----
        __syncthreads();
        #pragma unroll
        for (int i = tid; i < TB * Dd / 4; i += NT) {
            float4 xv = sx4[i];
            const float4 vv = sv4[i];
            xv.x += C4DT * vv.x; xv.y += C4DT * vv.y;
            xv.z += C4DT * vv.z; xv.w += C4DT * vv.w;
            sx4[i] = xv;
        }
    }

    // ---- store: out = [x ; v] ----
    __syncthreads();
    {
        float4* ox = (float4*)(out + (size_t)row0 * Dd);
        float4* ov = (float4*)(out + (size_t)Bsz * Dd + (size_t)row0 * Dd);
        #pragma unroll
        for (int i = tid; i < TB * Dd / 4; i += NT) {
            ox[i] = sx4[i];
            ov[i] = sv4[i];
        }
    }
}

extern "C" void kernel_launch(void* const* d_in, const int* in_sizes, int n_in,
                              void* d_out, int out_size) {
    const float* x     = (const float*)d_in[0];
    const float* v     = (const float*)d_in[1];
    const float* force = (const float*)d_in[2];
    const float* U     = (const float*)d_in[3];
    const float* W     = (const float*)d_in[4];
    const float* Vw    = (const float*)d_in[5];
    const int*   steps = (const int*)d_in[6];

    const size_t smem = (size_t)(2 * TB * Dd + Rr * TB + TB) * sizeof(float)
                      + (size_t)7 * 1024 * sizeof(ull);
    cudaFuncSetAttribute(yoshida_kernel,
                         cudaFuncAttributeMaxDynamicSharedMemorySize, (int)smem);
    yoshida_kernel<<<Bsz / TB, NT, smem>>>(x, v, force, U, W, Vw, steps, (float*)d_out);
}

// round 5
// speedup vs baseline: 2.1653x; 1.0871x over previous
#include <cuda_runtime.h>
#include <math.h>

#define Bsz 8192
#define Dd  1024
#define Rr  64
#define TB  16
#define NT  512

typedef unsigned long long ull;

// ---- Yoshida 4th-order coefficients ----
constexpr double kCbrt2 = 1.2599210498948731647672106072782;
constexpr double kW1 = 1.0 / (2.0 - kCbrt2);
constexpr double kW0 = -kCbrt2 * kW1;
constexpr double kDT = 0.01;

#define C1DT ((float)((kW1 * 0.5) * kDT))
#define C2DT ((float)(((kW0 + kW1) * 0.5) * kDT))
#define C4DT C1DT
#define D1DT ((float)(kW1 * kDT))
#define D2DT ((float)(kW0 * kDT))

#define PLASTICITY    0.1f
#define SING_THRESH   10.0f
#define SING_STRENGTH 20.0f

// ---- packed f32x2 helpers (Blackwell) ----
__device__ __forceinline__ ull splat2(float x) {
    ull r; asm("mov.b64 %0, {%1, %1};" : "=l"(r) : "f"(x)); return r;
}
__device__ __forceinline__ ull fma2(ull a, ull b, ull c) {
    ull d; asm("fma.rn.f32x2 %0, %1, %2, %3;" : "=l"(d) : "l"(a), "l"(b), "l"(c)); return d;
}
__device__ __forceinline__ ull add2(ull a, ull b) {
    ull d; asm("add.rn.f32x2 %0, %1, %2;" : "=l"(d) : "l"(a), "l"(b)); return d;
}
__device__ __forceinline__ float2 unpk2(ull v) {
    float2 r; asm("mov.b64 {%0, %1}, %2;" : "=f"(r.x), "=f"(r.y) : "l"(v)); return r;
}

// One rank-projection pass: A[j*2+h] accumulates (st_row(w8+j) . mat[:, rq+2h, rq+2h+1])
// over this thread's 64-d slice. 8 rows x 4 r's per thread, FMA2-paired over r.
__device__ __forceinline__ void rank_pass(const float* __restrict__ st,
                                          const float* __restrict__ mat,
                                          int rq, int w8, int d0, ull* A)
{
    #pragma unroll
    for (int c = 0; c < 16; ++c) A[c] = 0ull;
    const float* sb = st + (size_t)w8 * Dd + d0;
    const float* mb = mat + (size_t)d0 * Rr + rq;
    #pragma unroll 1
    for (int d = 0; d < 64; d += 4) {
        ulonglong2 u[4];
        #pragma unroll
        for (int dd = 0; dd < 4; ++dd)
            u[dd] = *(const ulonglong2*)(mb + (size_t)(d + dd) * Rr);
        float4 sv[8];
        #pragma unroll
        for (int j = 0; j < 8; ++j)
            sv[j] = *(const float4*)(sb + j * Dd + d);
        #pragma unroll
        for (int dd = 0; dd < 4; ++dd) {
            #pragma unroll
            for (int j = 0; j < 8; ++j) {
                const float f = (dd == 0) ? sv[j].x : (dd == 1) ? sv[j].y
                              : (dd == 2) ? sv[j].z : sv[j].w;
                const ull sp = splat2(f);
                A[j * 2 + 0] = fma2(sp, u[dd].x, A[j * 2 + 0]);
                A[j * 2 + 1] = fma2(sp, u[dd].y, A[j * 2 + 1]);
            }
        }
    }
}

__global__ void __launch_bounds__(NT, 1)
yoshida_kernel(const float* __restrict__ x_in,
               const float* __restrict__ v_in,
               const float* __restrict__ force,
               const float* __restrict__ U,     // [D, R]
               const float* __restrict__ Wm,    // [R, D]
               const float* __restrict__ Vw,    // [D, R]
               const int*   __restrict__ steps_p,
               float* __restrict__ out)         // [x(B*D) ; v(B*D)]
{
    extern __shared__ float smem[];
    float* xs     = smem;                       // 16384 floats
    float* vs     = xs + TB * Dd;               // 16384
    float* qs     = vs + TB * Dd;               // 1024  (qs[r*TB + row], sing folded)
    float* sing_s = qs + Rr * TB;               // 16
    ull*   part   = (ull*)(sing_s + TB);        // 8192 ull = 64KB (partials, reused P/M)
    ull*   Pred   = part + 16 * 512;            // 512 ull = 4KB (reduced P)

    const int tid  = threadIdx.x;
    const int row0 = blockIdx.x * TB;

    float4* sx4 = (float4*)xs;
    float4* sv4 = (float4*)vs;

    // ---- phase-2 mapping: 16 r-quads x 2 row-octets x 16 d-slices ----
    const int rq  = (tid & 15) * 4;
    const int w8a = ((tid >> 4) & 1) * 8;
    const int ds  = tid >> 5;                   // 0..15
    const int grp = tid & 31;                   // (wg,rqi)
    // ---- reduce mapping: 32 groups x 16 components ----
    const int rc  = tid >> 5;                   // component 0..15
    // ---- phase-3 mapping: 256 k-quads x 2 row-octets ----
    const int k4  = (tid & 255) * 4;
    const int w8b = (tid >> 8) * 8;

    // ---- load state tile ----
    {
        const float4* gx = (const float4*)(x_in + (size_t)row0 * Dd);
        const float4* gv = (const float4*)(v_in + (size_t)row0 * Dd);
        #pragma unroll
        for (int i = tid; i < TB * Dd / 4; i += NT) {
            sx4[i] = gx[i];
            sv4[i] = gv[i];
        }
    }

    const int nsteps = *steps_p;

    for (int s = 0; s < nsteps; ++s) {
        #pragma unroll 1
        for (int sub = 0; sub < 3; ++sub) {
            const float cdt = (sub == 0) ? C1DT : C2DT;                    // C3 == C2
            const float ddt = (sub == 1) ? D2DT : D1DT;                    // D3 == D1

            // ---- drift: x += cdt * v ----
            __syncthreads();
            #pragma unroll
            for (int i = tid; i < TB * Dd / 4; i += NT) {
                float4 xv = sx4[i];
                const float4 vv = sv4[i];
                xv.x += cdt * vv.x; xv.y += cdt * vv.y;
                xv.z += cdt * vv.z; xv.w += cdt * vv.w;
                sx4[i] = xv;
            }
            __syncthreads();

            // ---- phase 1: xn2 per row -> sing (one warp per row) ----
            {
                const int row  = tid >> 5;
                const int lane = tid & 31;
                const float4* xr = (const float4*)(xs + row * Dd);
                float acc = 0.0f;
                #pragma unroll
                for (int i = 0; i < 8; ++i) {
                    const float4 xv = xr[lane + i * 32];
                    acc += xv.x * xv.x + xv.y * xv.y + xv.z * xv.z + xv.w * xv.w;
                }
                #pragma unroll
                for (int o = 16; o; o >>= 1)
                    acc += __shfl_xor_sync(0xffffffffu, acc, o);
                if (lane == 0)
                    sing_s[row] = 1.0f + SING_STRENGTH * expf(-acc * (1.0f / SING_THRESH));
            }

            ull A[16];

            // ---- P-pass: P = v.U ----
            rank_pass(vs, U, rq, w8a, ds * 64, A);
            #pragma unroll
            for (int c = 0; c < 16; ++c)
                part[c * 512 + ds * 32 + grp] = A[c];
            __syncthreads();

            // ---- P-reduce: each thread reduces one (component, group) over 16 slices ----
            {
                ull acc = part[rc * 512 + grp];
                #pragma unroll
                for (int p = 1; p < 16; ++p)
                    acc = add2(acc, part[rc * 512 + p * 32 + grp]);
                Pred[rc * 32 + grp] = acc;
            }
            __syncthreads();   // protect part[] reads before M-pass overwrites

            // ---- M-pass: M = x.Vw ----
            rank_pass(xs, Vw, rq, w8a, ds * 64, A);
            #pragma unroll
            for (int c = 0; c < 16; ++c)
                part[c * 512 + ds * 32 + grp] = A[c];
            __syncthreads();

            // ---- M-reduce + q epilogue (sing folded into q) ----
            {
                ull acc = part[rc * 512 + grp];
                #pragma unroll
                for (int p = 1; p < 16; ++p)
                    acc = add2(acc, part[rc * 512 + p * 32 + grp]);
                const float2 m = unpk2(acc);
                const float2 pv = unpk2(Pred[rc * 32 + grp]);
                const int h    = rc & 1;
                const int j    = rc >> 1;
                const int rowq = (grp >> 4) * 8 + j;
                const int rr   = (grp & 15) * 4 + h * 2;
                const float sg = sing_s[rowq];
                qs[(rr + 0) * TB + rowq] = pv.x * pv.x * (1.0f + PLASTICITY * tanhf(m.x)) * sg;
                qs[(rr + 1) * TB + rowq] = pv.y * pv.y * (1.0f + PLASTICITY * tanhf(m.y)) * sg;
            }
            __syncthreads();

            // ---- phase 3: gamma = q.W (FMA2 over row-pairs); v += ddt*(force - gamma) ----
            {
                ull Acc[16];   // Acc[k*4 + rowpair]
                #pragma unroll
                for (int c = 0; c < 16; ++c) Acc[c] = 0ull;

                #pragma unroll 1
                for (int r = 0; r < Rr; r += 2) {
                    const float4 w0 = *(const float4*)(Wm + (size_t)r * Dd + k4);
                    const float4 w1 = *(const float4*)(Wm + (size_t)(r + 1) * Dd + k4);
                    const ulonglong2 qa0 = *(const ulonglong2*)(qs + r * TB + w8b);
                    const ulonglong2 qb0 = *(const ulonglong2*)(qs + r * TB + w8b + 4);
                    const ulonglong2 qa1 = *(const ulonglong2*)(qs + (r + 1) * TB + w8b);
                    const ulonglong2 qb1 = *(const ulonglong2*)(qs + (r + 1) * TB + w8b + 4);
                    {
                        const ull s0 = splat2(w0.x), s1 = splat2(w0.y);
                        const ull s2 = splat2(w0.z), s3 = splat2(w0.w);
                        Acc[0]  = fma2(qa0.x, s0, Acc[0]);  Acc[1]  = fma2(qa0.y, s0, Acc[1]);
                        Acc[2]  = fma2(qb0.x, s0, Acc[2]);  Acc[3]  = fma2(qb0.y, s0, Acc[3]);
                        Acc[4]  = fma2(qa0.x, s1, Acc[4]);  Acc[5]  = fma2(qa0.y, s1, Acc[5]);
                        Acc[6]  = fma2(qb0.x, s1, Acc[6]);  Acc[7]  = fma2(qb0.y, s1, Acc[7]);
                        Acc[8]  = fma2(qa0.x, s2, Acc[8]);  Acc[9]  = fma2(qa0.y, s2, Acc[9]);
                        Acc[10] = fma2(qb0.x, s2, Acc[10]); Acc[11] = fma2(qb0.y, s2, Acc[11]);
                        Acc[12] = fma2(qa0.x, s3, Acc[12]); Acc[13] = fma2(qa0.y, s3, Acc[13]);
                        Acc[14] = fma2(qb0.x, s3, Acc[14]); Acc[15] = fma2(qb0.y, s3, Acc[15]);
                    }
                    {
                        const ull s0 = splat2(w1.x), s1 = splat2(w1.y);
                        const ull s2 = splat2(w1.z), s3 = splat2(w1.w);
                        Acc[0]  = fma2(qa1.x, s0, Acc[0]);  Acc[1]  = fma2(qa1.y, s0, Acc[1]);
                        Acc[2]  = fma2(qb1.x, s0, Acc[2]);  Acc[3]  = fma2(qb1.y, s0, Acc[3]);
                        Acc[4]  = fma2(qa1.x, s1, Acc[4]);  Acc[5]  = fma2(qa1.y, s1, Acc[5]);
                        Acc[6]  = fma2(qb1.x, s1, Acc[6]);  Acc[7]  = fma2(qb1.y, s1, Acc[7]);
                        Acc[8]  = fma2(qa1.x, s2, Acc[8]);  Acc[9]  = fma2(qa1.y, s2, Acc[9]);
                        Acc[10] = fma2(qb1.x, s2, Acc[10]); Acc[11] = fma2(qb1.y, s2, Acc[11]);
                        Acc[12] = fma2(qa1.x, s3, Acc[12]); Acc[13] = fma2(qa1.y, s3, Acc[13]);
                        Acc[14] = fma2(qb1.x, s3, Acc[14]); Acc[15] = fma2(qb1.y, s3, Acc[15]);
                    }
                }

                #pragma unroll
                for (int p = 0; p < 4; ++p) {
                    const float2 g0 = unpk2(Acc[0 * 4 + p]);
                    const float2 g1 = unpk2(Acc[1 * 4 + p]);
                    const float2 g2 = unpk2(Acc[2 * 4 + p]);
                    const float2 g3 = unpk2(Acc[3 * 4 + p]);
                    const int re = w8b + 2 * p;
                    {
                        const float4 f = *(const float4*)(force + (size_t)(row0 + re) * Dd + k4);
                        float4* vp = (float4*)(vs + re * Dd + k4);
                        float4 vv = *vp;
                        vv.x += ddt * (f.x - g0.x);
                        vv.y += ddt * (f.y - g1.x);
                        vv.z += ddt * (f.z - g2.x);
                        vv.w += ddt * (f.w - g3.x);
                        *vp = vv;
                    }
                    {
                        const int ro = re + 1;
                        const float4 f = *(const float4*)(force + (size_t)(row0 + ro) * Dd + k4);
                        float4* vp = (float4*)(vs + ro * Dd + k4);
                        float4 vv = *vp;
                        vv.x += ddt * (f.x - g0.y);
                        vv.y += ddt * (f.y - g1.y);
                        vv.z += ddt * (f.z - g2.y);
                        vv.w += ddt * (f.w - g3.y);
                        *vp = vv;
                    }
                }
            }
        }

        // ---- final drift of the step: x += C4*dt * v ----
        __syncthreads();
        #pragma unroll
        for (int i = tid; i < TB * Dd / 4; i += NT) {
            float4 xv = sx4[i];
            const float4 vv = sv4[i];
            xv.x += C4DT * vv.x; xv.y += C4DT * vv.y;
            xv.z += C4DT * vv.z; xv.w += C4DT * vv.w;
            sx4[i] = xv;
        }
    }

    // ---- store: out = [x ; v] ----
    __syncthreads();
    {
        float4* ox = (float4*)(out + (size_t)row0 * Dd);
        float4* ov = (float4*)(out + (size_t)Bsz * Dd + (size_t)row0 * Dd);
        #pragma unroll
        for (int i = tid; i < TB * Dd / 4; i += NT) {
            ox[i] = sx4[i];
            ov[i] = sv4[i];
        }
    }
}

extern "C" void kernel_launch(void* const* d_in, const int* in_sizes, int n_in,
                              void* d_out, int out_size) {
    const float* x     = (const float*)d_in[0];
    const float* v     = (const float*)d_in[1];
    const float* force = (const float*)d_in[2];
    const float* U     = (const float*)d_in[3];
    const float* W     = (const float*)d_in[4];
    const float* Vw    = (const float*)d_in[5];
    const int*   steps = (const int*)d_in[6];

    const size_t smem = (size_t)(2 * TB * Dd + Rr * TB + TB) * sizeof(float)
                      + (size_t)(16 * 512 + 512) * sizeof(ull);
    cudaFuncSetAttribute(yoshida_kernel,
                         cudaFuncAttributeMaxDynamicSharedMemorySize, (int)smem);
    yoshida_kernel<<<Bsz / TB, NT, smem>>>(x, v, force, U, W, Vw, steps, (float*)d_out);
}

// round 6
// speedup vs baseline: 2.3942x; 1.1057x over previous
#include <cuda_runtime.h>
#include <math.h>

#define Bsz 8192
#define Dd  1024
#define Rr  64
#define TB  16
#define NT  512

typedef unsigned long long ull;

// ---- Yoshida 4th-order coefficients ----
constexpr double kCbrt2 = 1.2599210498948731647672106072782;
constexpr double kW1 = 1.0 / (2.0 - kCbrt2);
constexpr double kW0 = -kCbrt2 * kW1;
constexpr double kDT = 0.01;

#define C1DT ((float)((kW1 * 0.5) * kDT))
#define C2DT ((float)(((kW0 + kW1) * 0.5) * kDT))
#define C4DT C1DT
#define D1DT ((float)(kW1 * kDT))
#define D2DT ((float)(kW0 * kDT))

#define PLASTICITY    0.1f
#define SING_THRESH   10.0f
#define SING_STRENGTH 20.0f

// ---- packed f32x2 helpers (Blackwell) ----
__device__ __forceinline__ ull splat2(float x) {
    ull r; asm("mov.b64 %0, {%1, %1};" : "=l"(r) : "f"(x)); return r;
}
__device__ __forceinline__ ull fma2(ull a, ull b, ull c) {
    ull d; asm("fma.rn.f32x2 %0, %1, %2, %3;" : "=l"(d) : "l"(a), "l"(b), "l"(c)); return d;
}
__device__ __forceinline__ ull add2(ull a, ull b) {
    ull d; asm("add.rn.f32x2 %0, %1, %2;" : "=l"(d) : "l"(a), "l"(b)); return d;
}
__device__ __forceinline__ float2 unpk2(ull v) {
    float2 r; asm("mov.b64 {%0, %1}, %2;" : "=f"(r.x), "=f"(r.y) : "l"(v)); return r;
}

// Process one 4-d block: 8 rows x 4 r's, in two 4-row halves to limit registers.
__device__ __forceinline__ void block_fma(const float* __restrict__ sb, int d,
                                          const ulonglong2* u, ull* A)
{
    #pragma unroll
    for (int half = 0; half < 2; ++half) {
        float4 sv[4];
        #pragma unroll
        for (int j = 0; j < 4; ++j)
            sv[j] = *(const float4*)(sb + (half * 4 + j) * Dd + d);
        ull* Ah = A + half * 8;
        #pragma unroll
        for (int dd = 0; dd < 4; ++dd) {
            #pragma unroll
            for (int j = 0; j < 4; ++j) {
                const float f = (dd == 0) ? sv[j].x : (dd == 1) ? sv[j].y
                              : (dd == 2) ? sv[j].z : sv[j].w;
                const ull sp = splat2(f);
                Ah[j * 2 + 0] = fma2(sp, u[dd].x, Ah[j * 2 + 0]);
                Ah[j * 2 + 1] = fma2(sp, u[dd].y, Ah[j * 2 + 1]);
            }
        }
    }
}

// Rank pass with software-pipelined matrix LDG (one 4-d block ahead).
__device__ __forceinline__ void rank_pass(const float* __restrict__ st,
                                          const float* __restrict__ mat,
                                          int rq, int w8, int d0, ull* A)
{
    #pragma unroll
    for (int c = 0; c < 16; ++c) A[c] = 0ull;
    const float* sb = st + (size_t)w8 * Dd + d0;
    const float* mb = mat + (size_t)d0 * Rr + rq;

    ulonglong2 u[4];
    #pragma unroll
    for (int dd = 0; dd < 4; ++dd)
        u[dd] = *(const ulonglong2*)(mb + (size_t)dd * Rr);

    #pragma unroll 1
    for (int d = 0; d < 60; d += 4) {
        ulonglong2 un[4];
        #pragma unroll
        for (int dd = 0; dd < 4; ++dd)
            un[dd] = *(const ulonglong2*)(mb + (size_t)(d + 4 + dd) * Rr);
        block_fma(sb, d, u, A);
        #pragma unroll
        for (int dd = 0; dd < 4; ++dd) u[dd] = un[dd];
    }
    block_fma(sb, 60, u, A);
}

__global__ void __launch_bounds__(NT, 1)
yoshida_kernel(const float* __restrict__ x_in,
               const float* __restrict__ v_in,
               const float* __restrict__ force,
               const float* __restrict__ U,     // [D, R]
               const float* __restrict__ Wm,    // [R, D]
               const float* __restrict__ Vw,    // [D, R]
               const int*   __restrict__ steps_p,
               float* __restrict__ out)         // [x(B*D) ; v(B*D)]
{
    extern __shared__ float smem[];
    float* xs     = smem;                       // 16384 floats
    float* vs     = xs + TB * Dd;               // 16384
    float* qs     = vs + TB * Dd;               // 1024  (qs[r*TB + row], sing folded)
    float* sing_s = qs + Rr * TB;               // 16
    ull*   part   = (ull*)(sing_s + TB);        // 8192 ull = 64KB (partials, reused P/M)
    ull*   Pred   = part + 16 * 512;            // 512 ull = 4KB (reduced P)

    const int tid  = threadIdx.x;
    const int row0 = blockIdx.x * TB;

    float4* sx4 = (float4*)xs;
    float4* sv4 = (float4*)vs;

    // ---- phase-2 mapping: 16 r-quads x 2 row-octets x 16 d-slices ----
    const int rq  = (tid & 15) * 4;
    const int w8a = ((tid >> 4) & 1) * 8;
    const int ds  = tid >> 5;                   // 0..15
    const int grp = tid & 31;                   // (wg,rqi)
    // ---- reduce mapping: 32 groups x 16 components ----
    const int rc  = tid >> 5;                   // component 0..15
    // ---- phase-3 mapping: 256 k-quads x 2 row-octets ----
    const int k4  = (tid & 255) * 4;
    const int w8b = (tid >> 8) * 8;

    // ---- load state tile ----
    {
        const float4* gx = (const float4*)(x_in + (size_t)row0 * Dd);
        const float4* gv = (const float4*)(v_in + (size_t)row0 * Dd);
        #pragma unroll
        for (int i = tid; i < TB * Dd / 4; i += NT) {
            sx4[i] = gx[i];
            sv4[i] = gv[i];
        }
    }

    const int nsteps = *steps_p;

    for (int s = 0; s < nsteps; ++s) {
        #pragma unroll 1
        for (int sub = 0; sub < 3; ++sub) {
            const float cdt = (sub == 0) ? C1DT : C2DT;                    // C3 == C2
            const float ddt = (sub == 1) ? D2DT : D1DT;                    // D3 == D1

            // ---- drift: x += cdt * v ----
            __syncthreads();
            #pragma unroll
            for (int i = tid; i < TB * Dd / 4; i += NT) {
                float4 xv = sx4[i];
                const float4 vv = sv4[i];
                xv.x += cdt * vv.x; xv.y += cdt * vv.y;
                xv.z += cdt * vv.z; xv.w += cdt * vv.w;
                sx4[i] = xv;
            }
            __syncthreads();

            // ---- phase 1: xn2 per row -> sing (one warp per row) ----
            {
                const int row  = tid >> 5;
                const int lane = tid & 31;
                const float4* xr = (const float4*)(xs + row * Dd);
                float acc = 0.0f;
                #pragma unroll
                for (int i = 0; i < 8; ++i) {
                    const float4 xv = xr[lane + i * 32];
                    acc += xv.x * xv.x + xv.y * xv.y + xv.z * xv.z + xv.w * xv.w;
                }
                #pragma unroll
                for (int o = 16; o; o >>= 1)
                    acc += __shfl_xor_sync(0xffffffffu, acc, o);
                if (lane == 0)
                    sing_s[row] = 1.0f + SING_STRENGTH * expf(-acc * (1.0f / SING_THRESH));
            }

            ull A[16];

            // ---- P-pass: P = v.U ----
            rank_pass(vs, U, rq, w8a, ds * 64, A);
            #pragma unroll
            for (int c = 0; c < 16; ++c)
                part[c * 512 + ds * 32 + grp] = A[c];
            __syncthreads();

            // ---- P-reduce ----
            {
                ull acc = part[rc * 512 + grp];
                #pragma unroll
                for (int p = 1; p < 16; ++p)
                    acc = add2(acc, part[rc * 512 + p * 32 + grp]);
                Pred[rc * 32 + grp] = acc;
            }
            __syncthreads();   // protect part[] reads before M-pass overwrites

            // ---- M-pass: M = x.Vw ----
            rank_pass(xs, Vw, rq, w8a, ds * 64, A);
            #pragma unroll
            for (int c = 0; c < 16; ++c)
                part[c * 512 + ds * 32 + grp] = A[c];
            __syncthreads();

            // ---- M-reduce + q epilogue (sing folded into q) ----
            {
                ull acc = part[rc * 512 + grp];
                #pragma unroll
                for (int p = 1; p < 16; ++p)
                    acc = add2(acc, part[rc * 512 + p * 32 + grp]);
                const float2 m = unpk2(acc);
                const float2 pv = unpk2(Pred[rc * 32 + grp]);
                const int h    = rc & 1;
                const int j    = rc >> 1;
                const int rowq = (grp >> 4) * 8 + j;
                const int rr   = (grp & 15) * 4 + h * 2;
                const float sg = sing_s[rowq];
                qs[(rr + 0) * TB + rowq] = pv.x * pv.x * (1.0f + PLASTICITY * tanhf(m.x)) * sg;
                qs[(rr + 1) * TB + rowq] = pv.y * pv.y * (1.0f + PLASTICITY * tanhf(m.y)) * sg;
            }
            __syncthreads();

            // ---- phase 3: gamma = q.W (FMA2 over row-pairs, W prefetched);
            //      v += ddt*(force - gamma) ----
            {
                ull Acc[16];   // Acc[k*4 + rowpair]
                #pragma unroll
                for (int c = 0; c < 16; ++c) Acc[c] = 0ull;

                float4 w0 = *(const float4*)(Wm + k4);
                float4 w1 = *(const float4*)(Wm + Dd + k4);

                #pragma unroll 1
                for (int r = 0; r < Rr; r += 2) {
                    float4 w0n, w1n;
                    if (r < Rr - 2) {
                        w0n = *(const float4*)(Wm + (size_t)(r + 2) * Dd + k4);
                        w1n = *(const float4*)(Wm + (size_t)(r + 3) * Dd + k4);
                    }
                    const ulonglong2 qa0 = *(const ulonglong2*)(qs + r * TB + w8b);
                    const ulonglong2 qb0 = *(const ulonglong2*)(qs + r * TB + w8b + 4);
                    const ulonglong2 qa1 = *(const ulonglong2*)(qs + (r + 1) * TB + w8b);
                    const ulonglong2 qb1 = *(const ulonglong2*)(qs + (r + 1) * TB + w8b + 4);
                    {
                        const ull s0 = splat2(w0.x), s1 = splat2(w0.y);
                        const ull s2 = splat2(w0.z), s3 = splat2(w0.w);
                        Acc[0]  = fma2(qa0.x, s0, Acc[0]);  Acc[1]  = fma2(qa0.y, s0, Acc[1]);
                        Acc[2]  = fma2(qb0.x, s0, Acc[2]);  Acc[3]  = fma2(qb0.y, s0, Acc[3]);
                        Acc[4]  = fma2(qa0.x, s1, Acc[4]);  Acc[5]  = fma2(qa0.y, s1, Acc[5]);
                        Acc[6]  = fma2(qb0.x, s1, Acc[6]);  Acc[7]  = fma2(qb0.y, s1, Acc[7]);
                        Acc[8]  = fma2(qa0.x, s2, Acc[8]);  Acc[9]  = fma2(qa0.y, s2, Acc[9]);
                        Acc[10] = fma2(qb0.x, s2, Acc[10]); Acc[11] = fma2(qb0.y, s2, Acc[11]);
                        Acc[12] = fma2(qa0.x, s3, Acc[12]); Acc[13] = fma2(qa0.y, s3, Acc[13]);
                        Acc[14] = fma2(qb0.x, s3, Acc[14]); Acc[15] = fma2(qb0.y, s3, Acc[15]);
                    }
                    {
                        const ull s0 = splat2(w1.x), s1 = splat2(w1.y);
                        const ull s2 = splat2(w1.z), s3 = splat2(w1.w);
                        Acc[0]  = fma2(qa1.x, s0, Acc[0]);  Acc[1]  = fma2(qa1.y, s0, Acc[1]);
                        Acc[2]  = fma2(qb1.x, s0, Acc[2]);  Acc[3]  = fma2(qb1.y, s0, Acc[3]);
                        Acc[4]  = fma2(qa1.x, s1, Acc[4]);  Acc[5]  = fma2(qa1.y, s1, Acc[5]);
                        Acc[6]  = fma2(qb1.x, s1, Acc[6]);  Acc[7]  = fma2(qb1.y, s1, Acc[7]);
                        Acc[8]  = fma2(qa1.x, s2, Acc[8]);  Acc[9]  = fma2(qa1.y, s2, Acc[9]);
                        Acc[10] = fma2(qb1.x, s2, Acc[10]); Acc[11] = fma2(qb1.y, s2, Acc[11]);
                        Acc[12] = fma2(qa1.x, s3, Acc[12]); Acc[13] = fma2(qa1.y, s3, Acc[13]);
                        Acc[14] = fma2(qb1.x, s3, Acc[14]); Acc[15] = fma2(qb1.y, s3, Acc[15]);
                    }
                    w0 = w0n; w1 = w1n;
                }

                #pragma unroll
                for (int p = 0; p < 4; ++p) {
                    const float2 g0 = unpk2(Acc[0 * 4 + p]);
                    const float2 g1 = unpk2(Acc[1 * 4 + p]);
                    const float2 g2 = unpk2(Acc[2 * 4 + p]);
                    const float2 g3 = unpk2(Acc[3 * 4 + p]);
                    const int re = w8b + 2 * p;
                    {
                        const float4 f = *(const float4*)(force + (size_t)(row0 + re) * Dd + k4);
                        float4* vp = (float4*)(vs + re * Dd + k4);
                        float4 vv = *vp;
                        vv.x += ddt * (f.x - g0.x);
                        vv.y += ddt * (f.y - g1.x);
                        vv.z += ddt * (f.z - g2.x);
                        vv.w += ddt * (f.w - g3.x);
                        *vp = vv;
                    }
                    {
                        const int ro = re + 1;
                        const float4 f = *(const float4*)(force + (size_t)(row0 + ro) * Dd + k4);
                        float4* vp = (float4*)(vs + ro * Dd + k4);
                        float4 vv = *vp;
                        vv.x += ddt * (f.x - g0.y);
                        vv.y += ddt * (f.y - g1.y);
                        vv.z += ddt * (f.z - g2.y);
                        vv.w += ddt * (f.w - g3.y);
                        *vp = vv;
                    }
                }
            }
        }

        // ---- final drift of the step: x += C4*dt * v ----
        __syncthreads();
        #pragma unroll
        for (int i = tid; i < TB * Dd / 4; i += NT) {
            float4 xv = sx4[i];
            const float4 vv = sv4[i];
            xv.x += C4DT * vv.x; xv.y += C4DT * vv.y;
            xv.z += C4DT * vv.z; xv.w += C4DT * vv.w;
            sx4[i] = xv;
        }
    }

    // ---- store: out = [x ; v] ----
    __syncthreads();
    {
        float4* ox = (float4*)(out + (size_t)row0 * Dd);
        float4* ov = (float4*)(out + (size_t)Bsz * Dd + (size_t)row0 * Dd);
        #pragma unroll
        for (int i = tid; i < TB * Dd / 4; i += NT) {
            ox[i] = sx4[i];
            ov[i] = sv4[i];
        }
    }
}

extern "C" void kernel_launch(void* const* d_in, const int* in_sizes, int n_in,
                              void* d_out, int out_size) {
    const float* x     = (const float*)d_in[0];
    const float* v     = (const float*)d_in[1];
    const float* force = (const float*)d_in[2];
    const float* U     = (const float*)d_in[3];
    const float* W     = (const float*)d_in[4];
    const float* Vw    = (const float*)d_in[5];
    const int*   steps = (const int*)d_in[6];

    const size_t smem = (size_t)(2 * TB * Dd + Rr * TB + TB) * sizeof(float)
                      + (size_t)(16 * 512 + 512) * sizeof(ull);
    cudaFuncSetAttribute(yoshida_kernel,
                         cudaFuncAttributeMaxDynamicSharedMemorySize, (int)smem);
    yoshida_kernel<<<Bsz / TB, NT, smem>>>(x, v, force, U, W, Vw, steps, (float*)d_out);
}

// round 7
// speedup vs baseline: 2.4582x; 1.0267x over previous
#include <cuda_runtime.h>
#include <math.h>

#define Bsz 8192
#define Dd  1024
#define Rr  64
#define TB  16
#define NT  512

typedef unsigned long long ull;

// ---- Yoshida 4th-order coefficients ----
constexpr double kCbrt2 = 1.2599210498948731647672106072782;
constexpr double kW1 = 1.0 / (2.0 - kCbrt2);
constexpr double kW0 = -kCbrt2 * kW1;
constexpr double kDT = 0.01;

#define C1DT  ((float)((kW1 * 0.5) * kDT))
#define C2DT  ((float)(((kW0 + kW1) * 0.5) * kDT))
#define C4DT  C1DT
#define C41DT ((float)(kW1 * kDT))          // (C4 + C1) * dt
#define D1DT  ((float)(kW1 * kDT))
#define D2DT  ((float)(kW0 * kDT))

#define PLASTICITY    0.1f
#define SING_THRESH   10.0f
#define SING_STRENGTH 20.0f

// ---- packed f32x2 helpers (Blackwell) ----
__device__ __forceinline__ ull splat2(float x) {
    ull r; asm("mov.b64 %0, {%1, %1};" : "=l"(r) : "f"(x)); return r;
}
__device__ __forceinline__ ull fma2(ull a, ull b, ull c) {
    ull d; asm("fma.rn.f32x2 %0, %1, %2, %3;" : "=l"(d) : "l"(a), "l"(b), "l"(c)); return d;
}
__device__ __forceinline__ ull add2(ull a, ull b) {
    ull d; asm("add.rn.f32x2 %0, %1, %2;" : "=l"(d) : "l"(a), "l"(b)); return d;
}
__device__ __forceinline__ float2 unpk2(ull v) {
    float2 r; asm("mov.b64 {%0, %1}, %2;" : "=f"(r.x), "=f"(r.y) : "l"(v)); return r;
}

// Process one 4-d block: 8 rows x 4 r's, in two 4-row halves to limit registers.
__device__ __forceinline__ void block_fma(const float* __restrict__ sb, int d,
                                          const ulonglong2* u, ull* A)
{
    #pragma unroll
    for (int half = 0; half < 2; ++half) {
        float4 sv[4];
        #pragma unroll
        for (int j = 0; j < 4; ++j)
            sv[j] = *(const float4*)(sb + (half * 4 + j) * Dd + d);
        ull* Ah = A + half * 8;
        #pragma unroll
        for (int dd = 0; dd < 4; ++dd) {
            #pragma unroll
            for (int j = 0; j < 4; ++j) {
                const float f = (dd == 0) ? sv[j].x : (dd == 1) ? sv[j].y
                              : (dd == 2) ? sv[j].z : sv[j].w;
                const ull sp = splat2(f);
                Ah[j * 2 + 0] = fma2(sp, u[dd].x, Ah[j * 2 + 0]);
                Ah[j * 2 + 1] = fma2(sp, u[dd].y, Ah[j * 2 + 1]);
            }
        }
    }
}

// Rank pass with software-pipelined matrix LDG (one 4-d block ahead).
__device__ __forceinline__ void rank_pass(const float* __restrict__ st,
                                          const float* __restrict__ mat,
                                          int rq, int w8, int d0, ull* A)
{
    #pragma unroll
    for (int c = 0; c < 16; ++c) A[c] = 0ull;
    const float* sb = st + (size_t)w8 * Dd + d0;
    const float* mb = mat + (size_t)d0 * Rr + rq;

    ulonglong2 u[4];
    #pragma unroll
    for (int dd = 0; dd < 4; ++dd)
        u[dd] = *(const ulonglong2*)(mb + (size_t)dd * Rr);

    #pragma unroll 1
    for (int d = 0; d < 60; d += 4) {
        ulonglong2 un[4];
        #pragma unroll
        for (int dd = 0; dd < 4; ++dd)
            un[dd] = *(const ulonglong2*)(mb + (size_t)(d + 4 + dd) * Rr);
        block_fma(sb, d, u, A);
        #pragma unroll
        for (int dd = 0; dd < 4; ++dd) u[dd] = un[dd];
    }
    block_fma(sb, 60, u, A);
}

__global__ void __launch_bounds__(NT, 1)
yoshida_kernel(const float* __restrict__ x_in,
               const float* __restrict__ v_in,
               const float* __restrict__ force,
               const float* __restrict__ U,     // [D, R]
               const float* __restrict__ Wm,    // [R, D]
               const float* __restrict__ Vw,    // [D, R]
               const int*   __restrict__ steps_p,
               float* __restrict__ out)         // [x(B*D) ; v(B*D)]
{
    extern __shared__ float smem[];
    float* xs     = smem;                       // 16384 floats
    float* vs     = xs + TB * Dd;               // 16384
    float* qs     = vs + TB * Dd;               // 1024  (qs[r*TB + row], sing folded)
    float* sing_s = qs + Rr * TB;               // 16
    ull*   part   = (ull*)(sing_s + TB);        // 8192 ull = 64KB (partials, reused P/M)
    ull*   Pred   = part + 16 * 512;            // 512 ull = 4KB (reduced P)

    const int tid  = threadIdx.x;
    const int row0 = blockIdx.x * TB;

    float4* sx4 = (float4*)xs;
    float4* sv4 = (float4*)vs;

    // ---- phase-2 mapping: 16 r-quads x 2 row-octets x 16 d-slices ----
    const int rq  = (tid & 15) * 4;
    const int w8a = ((tid >> 4) & 1) * 8;
    const int ds  = tid >> 5;                   // 0..15
    const int grp = tid & 31;                   // (wg,rqi)
    // ---- reduce mapping: 32 groups x 16 components ----
    const int rc  = tid >> 5;                   // component 0..15
    // ---- phase-3 mapping: 256 k-quads x 2 row-octets ----
    const int k4  = (tid & 255) * 4;
    const int w8b = (tid >> 8) * 8;
    // ---- drift mapping: warp per row ----
    const int drow = tid >> 5;
    const int lane = tid & 31;

    // ---- load state tile ----
    {
        const float4* gx = (const float4*)(x_in + (size_t)row0 * Dd);
        const float4* gv = (const float4*)(v_in + (size_t)row0 * Dd);
        #pragma unroll
        for (int i = tid; i < TB * Dd / 4; i += NT) {
            sx4[i] = gx[i];
            sv4[i] = gv[i];
        }
    }

    const int nkicks = 3 * (*steps_p);

    for (int k = 0; k < nkicks; ++k) {
        const int sub = k - (k / 3) * 3;
        const float cdt = (k == 0) ? C1DT : (sub == 0) ? C41DT : C2DT;
        const float ddt = (sub == 1) ? D2DT : D1DT;

        __syncthreads();   // vs from prev kick visible; part free

        ull A[16];

        // ---- P-pass: P = v.U (pre-kick v; independent of drift) ----
        rank_pass(vs, U, rq, w8a, ds * 64, A);
        #pragma unroll
        for (int c = 0; c < 16; ++c)
            part[c * 512 + ds * 32 + grp] = A[c];

        // ---- drift + sing fused (warp per row, packed FMA2) ----
        {
            ulonglong2* xr = (ulonglong2*)(xs + drow * Dd);
            const ulonglong2* vr = (const ulonglong2*)(vs + drow * Dd);
            const ull cd2 = splat2(cdt);
            ull acc2 = 0ull;
            #pragma unroll
            for (int i = 0; i < 8; ++i) {
                ulonglong2 xv = xr[lane + 32 * i];
                const ulonglong2 vv = vr[lane + 32 * i];
                xv.x = fma2(cd2, vv.x, xv.x);
                xv.y = fma2(cd2, vv.y, xv.y);
                acc2 = fma2(xv.x, xv.x, acc2);
                acc2 = fma2(xv.y, xv.y, acc2);
                xr[lane + 32 * i] = xv;
            }
            const float2 a2 = unpk2(acc2);
            float acc = a2.x + a2.y;
            #pragma unroll
            for (int o = 16; o; o >>= 1)
                acc += __shfl_xor_sync(0xffffffffu, acc, o);
            if (lane == 0)
                sing_s[drow] = 1.0f + SING_STRENGTH * expf(-acc * (1.0f / SING_THRESH));
        }
        __syncthreads();

        // ---- P-reduce -> Pred ----
        {
            ull acc = part[rc * 512 + grp];
            #pragma unroll
            for (int p = 1; p < 16; ++p)
                acc = add2(acc, part[rc * 512 + p * 32 + grp]);
            Pred[rc * 32 + grp] = acc;
        }
        __syncthreads();   // part free for M-pass

        // ---- M-pass: M = x.Vw (drifted x) ----
        rank_pass(xs, Vw, rq, w8a, ds * 64, A);
        #pragma unroll
        for (int c = 0; c < 16; ++c)
            part[c * 512 + ds * 32 + grp] = A[c];
        __syncthreads();

        // ---- M-reduce + q epilogue (sing folded into q) ----
        {
            ull acc = part[rc * 512 + grp];
            #pragma unroll
            for (int p = 1; p < 16; ++p)
                acc = add2(acc, part[rc * 512 + p * 32 + grp]);
            const float2 m = unpk2(acc);
            const float2 pv = unpk2(Pred[rc * 32 + grp]);
            const int h    = rc & 1;
            const int j    = rc >> 1;
            const int rowq = (grp >> 4) * 8 + j;
            const int rr   = (grp & 15) * 4 + h * 2;
            const float sg = sing_s[rowq];
            qs[(rr + 0) * TB + rowq] = pv.x * pv.x * (1.0f + PLASTICITY * tanhf(m.x)) * sg;
            qs[(rr + 1) * TB + rowq] = pv.y * pv.y * (1.0f + PLASTICITY * tanhf(m.y)) * sg;
        }
        __syncthreads();

        // ---- phase 3: gamma = q.W (FMA2 over row-pairs, W prefetched);
        //      v += ddt*(force - gamma) ----
        {
            ull Acc[16];   // Acc[k*4 + rowpair]
            #pragma unroll
            for (int c = 0; c < 16; ++c) Acc[c] = 0ull;

            float4 w0 = *(const float4*)(Wm + k4);
            float4 w1 = *(const float4*)(Wm + Dd + k4);

            #pragma unroll 1
            for (int r = 0; r < Rr; r += 2) {
                float4 w0n, w1n;
                if (r < Rr - 2) {
                    w0n = *(const float4*)(Wm + (size_t)(r + 2) * Dd + k4);
                    w1n = *(const float4*)(Wm + (size_t)(r + 3) * Dd + k4);
                }
                const ulonglong2 qa0 = *(const ulonglong2*)(qs + r * TB + w8b);
                const ulonglong2 qb0 = *(const ulonglong2*)(qs + r * TB + w8b + 4);
                const ulonglong2 qa1 = *(const ulonglong2*)(qs + (r + 1) * TB + w8b);
                const ulonglong2 qb1 = *(const ulonglong2*)(qs + (r + 1) * TB + w8b + 4);
                {
                    const ull s0 = splat2(w0.x), s1 = splat2(w0.y);
                    const ull s2 = splat2(w0.z), s3 = splat2(w0.w);
                    Acc[0]  = fma2(qa0.x, s0, Acc[0]);  Acc[1]  = fma2(qa0.y, s0, Acc[1]);
                    Acc[2]  = fma2(qb0.x, s0, Acc[2]);  Acc[3]  = fma2(qb0.y, s0, Acc[3]);
                    Acc[4]  = fma2(qa0.x, s1, Acc[4]);  Acc[5]  = fma2(qa0.y, s1, Acc[5]);
                    Acc[6]  = fma2(qb0.x, s1, Acc[6]);  Acc[7]  = fma2(qb0.y, s1, Acc[7]);
                    Acc[8]  = fma2(qa0.x, s2, Acc[8]);  Acc[9]  = fma2(qa0.y, s2, Acc[9]);
                    Acc[10] = fma2(qb0.x, s2, Acc[10]); Acc[11] = fma2(qb0.y, s2, Acc[11]);
                    Acc[12] = fma2(qa0.x, s3, Acc[12]); Acc[13] = fma2(qa0.y, s3, Acc[13]);
                    Acc[14] = fma2(qb0.x, s3, Acc[14]); Acc[15] = fma2(qb0.y, s3, Acc[15]);
                }
                {
                    const ull s0 = splat2(w1.x), s1 = splat2(w1.y);
                    const ull s2 = splat2(w1.z), s3 = splat2(w1.w);
                    Acc[0]  = fma2(qa1.x, s0, Acc[0]);  Acc[1]  = fma2(qa1.y, s0, Acc[1]);
                    Acc[2]  = fma2(qb1.x, s0, Acc[2]);  Acc[3]  = fma2(qb1.y, s0, Acc[3]);
                    Acc[4]  = fma2(qa1.x, s1, Acc[4]);  Acc[5]  = fma2(qa1.y, s1, Acc[5]);
                    Acc[6]  = fma2(qb1.x, s1, Acc[6]);  Acc[7]  = fma2(qb1.y, s1, Acc[7]);
                    Acc[8]  = fma2(qa1.x, s2, Acc[8]);  Acc[9]  = fma2(qa1.y, s2, Acc[9]);
                    Acc[10] = fma2(qb1.x, s2, Acc[10]); Acc[11] = fma2(qb1.y, s2, Acc[11]);
                    Acc[12] = fma2(qa1.x, s3, Acc[12]); Acc[13] = fma2(qa1.y, s3, Acc[13]);
                    Acc[14] = fma2(qb1.x, s3, Acc[14]); Acc[15] = fma2(qb1.y, s3, Acc[15]);
                }
                w0 = w0n; w1 = w1n;
            }

            #pragma unroll
            for (int p = 0; p < 4; ++p) {
                const float2 g0 = unpk2(Acc[0 * 4 + p]);
                const float2 g1 = unpk2(Acc[1 * 4 + p]);
                const float2 g2 = unpk2(Acc[2 * 4 + p]);
                const float2 g3 = unpk2(Acc[3 * 4 + p]);
                const int re = w8b + 2 * p;
                {
                    const float4 f = *(const float4*)(force + (size_t)(row0 + re) * Dd + k4);
                    float4* vp = (float4*)(vs + re * Dd + k4);
                    float4 vv = *vp;
                    vv.x += ddt * (f.x - g0.x);
                    vv.y += ddt * (f.y - g1.x);
                    vv.z += ddt * (f.z - g2.x);
                    vv.w += ddt * (f.w - g3.x);
                    *vp = vv;
                }
                {
                    const int ro = re + 1;
                    const float4 f = *(const float4*)(force + (size_t)(row0 + ro) * Dd + k4);
                    float4* vp = (float4*)(vs + ro * Dd + k4);
                    float4 vv = *vp;
                    vv.x += ddt * (f.x - g0.y);
                    vv.y += ddt * (f.y - g1.y);
                    vv.z += ddt * (f.z - g2.y);
                    vv.w += ddt * (f.w - g3.y);
                    *vp = vv;
                }
            }
        }
    }

    // ---- store: out.x = xs + C4*dt*vs (final drift fused), out.v = vs ----
    __syncthreads();
    {
        const float fc = (nkicks > 0) ? C4DT : 0.0f;
        float4* ox = (float4*)(out + (size_t)row0 * Dd);
        float4* ov = (float4*)(out + (size_t)Bsz * Dd + (size_t)row0 * Dd);
        #pragma unroll
        for (int i = tid; i < TB * Dd / 4; i += NT) {
            const float4 xv = sx4[i];
            const float4 vv = sv4[i];
            float4 o;
            o.x = xv.x + fc * vv.x; o.y = xv.y + fc * vv.y;
            o.z = xv.z + fc * vv.z; o.w = xv.w + fc * vv.w;
            ox[i] = o;
            ov[i] = vv;
        }
    }
}

extern "C" void kernel_launch(void* const* d_in, const int* in_sizes, int n_in,
                              void* d_out, int out_size) {
    const float* x     = (const float*)d_in[0];
    const float* v     = (const float*)d_in[1];
    const float* force = (const float*)d_in[2];
    const float* U     = (const float*)d_in[3];
    const float* W     = (const float*)d_in[4];
    const float* Vw    = (const float*)d_in[5];
    const int*   steps = (const int*)d_in[6];

    const size_t smem = (size_t)(2 * TB * Dd + Rr * TB + TB) * sizeof(float)
                      + (size_t)(16 * 512 + 512) * sizeof(ull);
    cudaFuncSetAttribute(yoshida_kernel,
                         cudaFuncAttributeMaxDynamicSharedMemorySize, (int)smem);
    yoshida_kernel<<<Bsz / TB, NT, smem>>>(x, v, force, U, W, Vw, steps, (float*)d_out);
}